// round 8
// baseline (speedup 1.0000x reference)
#include <cuda_runtime.h>

#define L      4096
#define RPB    8                    // rows per block
#define HALF   2048                 // columns per block (half the row)
#define NTHR   256
#define GG     (HALF / 4 / NTHR)    // 2 float4 column-groups per thread
#define NBLK   ((L / RPB) * 2)      // 1024 blocks
#define CAP    (1 << 20)            // contact list capacity (expected ~168K)
#define K2BLK  128                  // kernel2 grid

__device__ double g_clash = 0.0;
__device__ double g_pair  = 0.0;
__device__ unsigned int g_nc    = 0;   // contact count (= n_pairs exactly)
__device__ unsigned int g_done2 = 0;
__device__ unsigned int g_list[CAP];   // key = (i << 12) | j

__device__ __forceinline__ float fsqrt_approx(float x) {
    float r;
    asm("sqrt.approx.f32 %0, %1;" : "=f"(r) : "f"(x));
    return r;
}

__device__ __forceinline__ float warp_sum(float v) {
    v += __shfl_down_sync(0xffffffffu, v, 16);
    v += __shfl_down_sync(0xffffffffu, v, 8);
    v += __shfl_down_sync(0xffffffffu, v, 4);
    v += __shfl_down_sync(0xffffffffu, v, 2);
    v += __shfl_down_sync(0xffffffffu, v, 1);
    return v;
}

// The ONE clash formula. Used by slow path and near-band correction ->
// identical inputs + identical ops -> exact cancellation of band terms.
__device__ __forceinline__ float clash_term(float xi, float yi, float zi,
                                            float xj, float yj, float zj) {
    float dx = xj - xi, dy = yj - yi, dz = zj - zi;
    float d2 = fmaf(dz, dz, fmaf(dy, dy, dx * dx));
    float d  = fsqrt_approx(d2) + 1e-8f;
    float t  = fmaxf(3.4f - d, 0.0f);
    return t * t;
}

// ---------------- kernel 1: O(L^2) sweep, NO sqrt in the hot loop ----------
__global__ void __launch_bounds__(NTHR, 4)
sweep_kernel(const float* __restrict__ coords,
             const float* __restrict__ cmap)
{
    __shared__ float sxi[RPB], syi[RPB], szi[RPB];
    __shared__ float red[8];
    const int tid  = threadIdx.x;
    const int rb   = blockIdx.x >> 1;
    const int half = blockIdx.x & 1;
    const int i0   = rb * RPB;

    if (tid < RPB) {
        sxi[tid] = __ldg(coords + 3 * (i0 + tid) + 0);
        syi[tid] = __ldg(coords + 3 * (i0 + tid) + 1);
        szi[tid] = __ldg(coords + 3 * (i0 + tid) + 2);
    }
    __syncthreads();

    float aclash = 0.0f;
    const float4* cp = (const float4*)coords;

#pragma unroll
    for (int gg = 0; gg < GG; ++gg) {
        const int g = half * (HALF / 4) + gg * NTHR + tid;  // float4 col group

        // stage 8 cmap rows: 8 independent DRAM LDG.128, one base address
        const float4* cbase = ((const float4*)(cmap + (size_t)i0 * L)) + g;
        float4 c[RPB];
#pragma unroll
        for (int r = 0; r < RPB; ++r) c[r] = __ldg(cbase + r * (L / 4));

        // 4 consecutive j coordinates: 3x LDG.128 (L2-hot)
        float4 q0 = __ldg(cp + 3 * g + 0);
        float4 q1 = __ldg(cp + 3 * g + 1);
        float4 q2 = __ldg(cp + 3 * g + 2);
        float xj[4] = {q0.x, q0.w, q1.z, q2.y};
        float yj[4] = {q0.y, q1.x, q1.w, q2.z};
        float zj[4] = {q0.z, q1.y, q2.x, q2.w};

        float maskA = 0.0f, maskB = 0.0f;   // contact bits via m=2m+cv (exact <2^16)
        float m2 = 1e30f;                   // min d^2 for clash vote

#pragma unroll
        for (int r = 0; r < RPB; ++r) {
            const float xi = sxi[r], yi = syi[r], zi = szi[r];
            const float4 cc = c[r];
            const float cv[4] = {cc.x, cc.y, cc.z, cc.w};
#pragma unroll
            for (int e = 0; e < 4; ++e) {
                float dx = xj[e] - xi;
                float dy = yj[e] - yi;
                float dz = zj[e] - zi;
                float d2 = fmaf(dz, dz, fmaf(dy, dy, dx * dx));
                m2 = fminf(m2, d2);
                if (r < 4) maskA = fmaf(maskA, 2.0f, cv[e]);
                else       maskB = fmaf(maskB, 2.0f, cv[e]);
            }
        }

        // clash slow path: only if some pair in this warp tile has d^2 < 12
        // (11.56 = 3.4^2 true threshold; margin swallows sqrt rounding).
        // Fast path contributes exactly 0 for all skipped pairs.
        if (__any_sync(0xffffffffu, m2 < 12.0f)) {
#pragma unroll
            for (int r = 0; r < RPB; ++r) {
                const float xi = sxi[r], yi = syi[r], zi = szi[r];
#pragma unroll
                for (int e = 0; e < 4; ++e)
                    aclash += clash_term(xi, yi, zi, xj[e], yj[e], zj[e]);
            }
        }

        // contact extraction: masks are tiny-popcount (~1% density)
        int ma = (int)maskA;      // bit (15 - (r*4+e)) for r in 0..3
        int mb = (int)maskB;      // bit (15 - ((r-4)*4+e)) for r in 4..7
        if (ma | mb) {
            const unsigned kbase = ((unsigned)i0 << 12) | (unsigned)(4 * g);
            while (ma) {
                int b = __ffs(ma) - 1; ma &= ma - 1;
                int pos = 15 - b;                 // r*4+e
                unsigned idx = atomicAdd(&g_nc, 1u);
                if (idx < CAP)
                    g_list[idx] = kbase + ((unsigned)(pos >> 2) << 12) + (pos & 3);
            }
            while (mb) {
                int b = __ffs(mb) - 1; mb &= mb - 1;
                int pos = 15 - b;
                unsigned idx = atomicAdd(&g_nc, 1u);
                if (idx < CAP)
                    g_list[idx] = kbase + ((unsigned)((pos >> 2) + 4) << 12) + (pos & 3);
            }
        }
    }

    // near-band correction: remove |j-i| <= 2 clash terms, same formula
    if (tid < RPB * 5) {
        const int r = tid / 5;
        const int o = tid % 5 - 2;
        const int i = i0 + r;
        const int j = i + o;
        if (j >= 0 && j < L && ((j >> 11) == half)) {
            float xJ = __ldg(coords + 3 * j + 0);
            float yJ = __ldg(coords + 3 * j + 1);
            float zJ = __ldg(coords + 3 * j + 2);
            aclash -= clash_term(sxi[r], syi[r], szi[r], xJ, yJ, zJ);
        }
    }

    // block reduce clash -> global
    aclash = warp_sum(aclash);
    const int wid  = tid >> 5;
    const int lane = tid & 31;
    if (lane == 0) red[wid] = aclash;
    __syncthreads();
    if (tid == 0) {
        float cs = 0.0f;
        for (int w = 0; w < 8; ++w) cs += red[w];
        atomicAdd(&g_clash, (double)cs);
    }
}

// ---------------- kernel 2: sparse contacts + bond + finalize --------------
__global__ void __launch_bounds__(NTHR)
pair_kernel(const float* __restrict__ coords, float* __restrict__ out)
{
    __shared__ float red[8];
    __shared__ float flast;
    const int tid  = threadIdx.x;
    const int wid  = tid >> 5;
    const int lane = tid & 31;

    const unsigned n = g_nc;
    float ap = 0.0f;
    for (unsigned k = blockIdx.x * NTHR + tid; k < n; k += K2BLK * NTHR) {
        unsigned key = g_list[k];
        int i = key >> 12, j = key & 4095;
        int sep = i - j; sep = sep < 0 ? -sep : sep;
        if (sep >= 3) {
            float dx = __ldg(coords + 3 * j + 0) - __ldg(coords + 3 * i + 0);
            float dy = __ldg(coords + 3 * j + 1) - __ldg(coords + 3 * i + 1);
            float dz = __ldg(coords + 3 * j + 2) - __ldg(coords + 3 * i + 2);
            float d  = fsqrt_approx(fmaf(dz, dz, fmaf(dy, dy, dx * dx))) + 1e-8f;
            float u  = d - 9.0f;                 // target = 6.0 * 1.5
            ap = fmaf(u, u, ap);
        }
    }
    ap = warp_sum(ap);
    if (lane == 0) red[wid] = ap;
    __syncthreads();
    if (tid == 0) {
        float ps = 0.0f;
        for (int w = 0; w < 8; ++w) ps += red[w];
        atomicAdd(&g_pair, (double)ps);
        __threadfence();
        unsigned prev = atomicAdd(&g_done2, 1u);
        flast = (prev == (unsigned)(K2BLK - 1)) ? 1.0f : 0.0f;
    }
    __syncthreads();

    if (flast != 0.0f) {
        float b = 0.0f;
        for (int k = tid; k < L - 1; k += NTHR) {
            float dx = __ldg(coords + 3 * k + 3) - __ldg(coords + 3 * k + 0);
            float dy = __ldg(coords + 3 * k + 4) - __ldg(coords + 3 * k + 1);
            float dz = __ldg(coords + 3 * k + 5) - __ldg(coords + 3 * k + 2);
            float d  = fsqrt_approx(fmaf(dz, dz, fmaf(dy, dy, dx * dx)));
            float t  = d - 6.0f;                 // IDEAL_C1_C1
            b = fmaf(t, t, b);
        }
        b = warp_sum(b);
        if (lane == 0) red[wid] = b;
        __syncthreads();
        if (tid == 0) {
            float bs = 0.0f;
            for (int w = 0; w < 8; ++w) bs += red[w];
            double e_bond  = (double)bs / (double)(L - 1);
            double e_clash = (g_clash * 0.5) / (double)L;   // sym sum -> upper tri
            double cnt     = (g_nc == 0u) ? 1.0 : (double)g_nc;
            double e_pair  = g_pair / cnt;
            out[0] = (float)(e_bond + 2.0 * e_clash + 0.5 * e_pair);
            // reset for next graph replay
            g_clash = 0.0;
            g_pair  = 0.0;
            g_nc    = 0u;
            g_done2 = 0u;
        }
    }
}

extern "C" void kernel_launch(void* const* d_in, const int* in_sizes, int n_in,
                              void* d_out, int out_size) {
    const float* a0 = (const float*)d_in[0];
    const float* a1 = (const float*)d_in[1];
    const float* coords = (in_sizes[0] < in_sizes[1]) ? a0 : a1;
    const float* cmap   = (in_sizes[0] < in_sizes[1]) ? a1 : a0;
    sweep_kernel<<<NBLK, NTHR>>>(coords, cmap);
    pair_kernel<<<K2BLK, NTHR>>>(coords, (float*)d_out);
}

// round 9
// speedup vs baseline: 1.7538x; 1.7538x over previous
#include <cuda_runtime.h>

#define L      4096
#define RPB    8                    // rows per block
#define HALF   2048                 // columns per block (half the row)
#define NTHR   256
#define GG     (HALF / 4 / NTHR)    // 2 float4 column-groups per thread
#define NBLK   ((L / RPB) * 2)      // 1024 blocks

typedef unsigned long long ull;

__device__ double g_clash = 0.0;
__device__ double g_pair  = 0.0;
__device__ double g_cnt   = 0.0;
__device__ unsigned int g_done = 0;

__device__ __forceinline__ float fsqrt_approx(float x) {
    float r;
    asm("sqrt.approx.f32 %0, %1;" : "=f"(r) : "f"(x));
    return r;
}

#define PACK2(o, lo, hi)   asm("mov.b64 %0, {%1, %2};" : "=l"(o) : "f"(lo), "f"(hi))
#define UNPACK2(lo, hi, i) asm("mov.b64 {%0, %1}, %2;" : "=f"(lo), "=f"(hi) : "l"(i))
#define ADD2(o, a, b)      asm("add.rn.f32x2 %0, %1, %2;" : "=l"(o) : "l"(a), "l"(b))
#define MUL2(o, a, b)      asm("mul.rn.f32x2 %0, %1, %2;" : "=l"(o) : "l"(a), "l"(b))
#define FMA2(o, a, b, c)   asm("fma.rn.f32x2 %0, %1, %2, %3;" : "=l"(o) : "l"(a), "l"(b), "l"(c))

__device__ __forceinline__ float warp_sum(float v) {
    v += __shfl_down_sync(0xffffffffu, v, 16);
    v += __shfl_down_sync(0xffffffffu, v, 8);
    v += __shfl_down_sync(0xffffffffu, v, 4);
    v += __shfl_down_sync(0xffffffffu, v, 2);
    v += __shfl_down_sync(0xffffffffu, v, 1);
    return v;
}

__global__ void __launch_bounds__(NTHR, 4)
energy_kernel(const float* __restrict__ coords,
              const float* __restrict__ cmap,
              float* __restrict__ out)
{
    __shared__ ull  s_nx[RPB], s_ny[RPB], s_nz[RPB];   // {-xi,-xi} packed f32x2
    __shared__ float red[64];
    const int tid  = threadIdx.x;
    const int rb   = blockIdx.x >> 1;        // row block
    const int half = blockIdx.x & 1;         // column half
    const int i0   = rb * RPB;

    if (tid < RPB) {
        float x = -__ldg(coords + 3 * (i0 + tid) + 0);
        float y = -__ldg(coords + 3 * (i0 + tid) + 1);
        float z = -__ldg(coords + 3 * (i0 + tid) + 2);
        ull px, py, pz;
        PACK2(px, x, x); PACK2(py, y, y); PACK2(pz, z, z);
        s_nx[tid] = px; s_ny[tid] = py; s_nz[tid] = pz;
    }
    __syncthreads();

    float clashA = 0.0f, clashB = 0.0f;   // includes |sep|<3 terms (corrected below)
    float pairA  = 0.0f, pairB  = 0.0f;
    float a_cnt  = 0.0f;                  // sum of contact values (exact 0/1)

    const float4* cp = (const float4*)coords;

#pragma unroll
    for (int gg = 0; gg < GG; ++gg) {
        const int g = half * (HALF / 4) + gg * NTHR + tid;  // float4 column group

        // stage 8 cmap rows first: 8 independent DRAM LDG.128, one base addr
        const float4* cbase = ((const float4*)(cmap + (size_t)i0 * L)) + g;
        float4 c[RPB];
#pragma unroll
        for (int r = 0; r < RPB; ++r) c[r] = __ldg(cbase + r * (L / 4));

        // 4 consecutive j coordinates: 3x LDG.128 (L2-hot), packed into f32x2
        float4 q0 = __ldg(cp + 3 * g + 0);      // x0 y0 z0 x1
        float4 q1 = __ldg(cp + 3 * g + 1);      // y1 z1 x2 y2
        float4 q2 = __ldg(cp + 3 * g + 2);      // z2 x3 y3 z3
        ull xj01, xj23, yj01, yj23, zj01, zj23;
        PACK2(xj01, q0.x, q0.w); PACK2(xj23, q1.z, q2.y);
        PACK2(yj01, q0.y, q1.x); PACK2(yj23, q1.w, q2.z);
        PACK2(zj01, q0.z, q1.y); PACK2(zj23, q2.x, q2.w);

#pragma unroll
        for (int r = 0; r < RPB; ++r) {
            const ull nx = s_nx[r], ny = s_ny[r], nz = s_nz[r];  // LDS.64 broadcast
            const float4 cc = c[r];

            ull dxA, dyA, dzA, sA, dxB, dyB, dzB, sB;
            ADD2(dxA, xj01, nx); ADD2(dyA, yj01, ny); ADD2(dzA, zj01, nz);
            ADD2(dxB, xj23, nx); ADD2(dyB, yj23, ny); ADD2(dzB, zj23, nz);
            MUL2(sA, dxA, dxA);  FMA2(sA, dyA, dyA, sA); FMA2(sA, dzA, dzA, sA);
            MUL2(sB, dxB, dxB);  FMA2(sB, dyB, dyB, sB); FMA2(sB, dzB, dzB, sB);
            float d2a, d2b, d2c, d2d;
            UNPACK2(d2a, d2b, sA);
            UNPACK2(d2c, d2d, sB);

            float da = fsqrt_approx(d2a);
            float db = fsqrt_approx(d2b);
            float dc = fsqrt_approx(d2c);
            float dd = fsqrt_approx(d2d);

            float ta = fmaxf(3.4f - da, 0.0f);
            float tb = fmaxf(3.4f - db, 0.0f);
            float tc = fmaxf(3.4f - dc, 0.0f);
            float td = fmaxf(3.4f - dd, 0.0f);
            clashA = fmaf(ta, ta, clashA);
            clashB = fmaf(tb, tb, clashB);
            clashA = fmaf(tc, tc, clashA);
            clashB = fmaf(td, td, clashB);

            float ua = da - 9.0f, ub = db - 9.0f, uc = dc - 9.0f, ud = dd - 9.0f;
            float wa = ua * cc.x, wb = ub * cc.y, wc = uc * cc.z, wd = ud * cc.w;
            pairA = fmaf(wa, ua, pairA);
            pairB = fmaf(wb, ub, pairB);
            pairA = fmaf(wc, uc, pairA);
            pairB = fmaf(wd, ud, pairB);

            a_cnt += (cc.x + cc.y) + (cc.z + cc.w);
        }
    }

    // Near-diagonal correction: remove |j-i| <= 2 terms. Only the column half
    // that owns column j performs it. Same fp ops/order as the main loop
    // (eps-free d, add-of-negated-xi) -> exact cancellation.
    if (tid < RPB * 5) {
        const int r = tid / 5;
        const int o = tid % 5 - 2;
        const int i = i0 + r;
        const int j = i + o;
        if (j >= 0 && j < L && ((j >> 11) == half)) {
            float nx, ny, nz, dum;
            UNPACK2(nx, dum, s_nx[r]);
            UNPACK2(ny, dum, s_ny[r]);
            UNPACK2(nz, dum, s_nz[r]);
            float xJ = __ldg(coords + 3 * j + 0);
            float yJ = __ldg(coords + 3 * j + 1);
            float zJ = __ldg(coords + 3 * j + 2);
            float dx = xJ + nx, dy = yJ + ny, dz = zJ + nz;
            float d2 = fmaf(dz, dz, fmaf(dy, dy, dx * dx));
            float d  = fsqrt_approx(d2);
            float t  = fmaxf(3.4f - d, 0.0f);
            clashA  -= t * t;
            float cv = __ldg(cmap + (size_t)i * L + j);
            float u  = d - 9.0f;
            float w  = u * cv;
            pairA    = fmaf(-w, u, pairA);
        }
    }

    // Block reduction
    float a_clash = clashA + clashB;
    float a_pair  = pairA + pairB;
    a_clash = warp_sum(a_clash);
    a_pair  = warp_sum(a_pair);
    a_cnt   = warp_sum(a_cnt);
    const int wid  = tid >> 5;
    const int lane = tid & 31;
    if (lane == 0) {
        red[wid]      = a_clash;
        red[8 + wid]  = a_pair;
        red[16 + wid] = a_cnt;
    }
    __syncthreads();
    if (tid == 0) {
        float cs = 0.0f, ps = 0.0f, ns = 0.0f;
        for (int w = 0; w < 8; ++w) { cs += red[w]; ps += red[8 + w]; ns += red[16 + w]; }
        atomicAdd(&g_clash, (double)cs);
        atomicAdd(&g_pair,  (double)ps);
        atomicAdd(&g_cnt,   (double)ns);
        __threadfence();
        unsigned prev = atomicAdd(&g_done, 1u);
        red[24] = (prev == (unsigned)(NBLK - 1)) ? 1.0f : 0.0f;
    }
    __syncthreads();

    // Last block: bond term + finalize + reset accumulators for next replay
    if (red[24] != 0.0f) {
        float b = 0.0f;
        for (int k = tid; k < L - 1; k += NTHR) {
            float dx = __ldg(coords + 3 * k + 3) - __ldg(coords + 3 * k + 0);
            float dy = __ldg(coords + 3 * k + 4) - __ldg(coords + 3 * k + 1);
            float dz = __ldg(coords + 3 * k + 5) - __ldg(coords + 3 * k + 2);
            float d  = fsqrt_approx(fmaf(dz, dz, fmaf(dy, dy, dx * dx)));
            float t  = d - 6.0f;               // IDEAL_C1_C1
            b = fmaf(t, t, b);
        }
        b = warp_sum(b);
        if (lane == 0) red[32 + wid] = b;
        __syncthreads();
        if (tid == 0) {
            float bs = 0.0f;
            for (int w = 0; w < 8; ++w) bs += red[32 + w];
            double e_bond  = (double)bs / (double)(L - 1);
            double e_clash = (g_clash * 0.5) / (double)L;     // sym sum -> upper triangle
            double cnt     = g_cnt < 1.0 ? 1.0 : g_cnt;
            double e_pair  = g_pair / cnt;
            out[0] = (float)(e_bond + 2.0 * e_clash + 0.5 * e_pair);
            // reset for next graph replay
            g_clash = 0.0;
            g_pair  = 0.0;
            g_cnt   = 0.0;
            g_done  = 0u;
        }
    }
}

extern "C" void kernel_launch(void* const* d_in, const int* in_sizes, int n_in,
                              void* d_out, int out_size) {
    const float* a0 = (const float*)d_in[0];
    const float* a1 = (const float*)d_in[1];
    // coords is the small input (L*3), contact_map the big one (L*L)
    const float* coords = (in_sizes[0] < in_sizes[1]) ? a0 : a1;
    const float* cmap   = (in_sizes[0] < in_sizes[1]) ? a1 : a0;
    energy_kernel<<<NBLK, NTHR>>>(coords, cmap, (float*)d_out);
}

// round 10
// speedup vs baseline: 2.1190x; 1.2082x over previous
#include <cuda_runtime.h>

#define L     4096
#define TS    64                      // tile size
#define NT    (L / TS)                // 64 tiles
#define NBLK  (NT * (NT + 1) / 2)     // 2080 tile pairs (A <= B)
#define NTHR  256
#define C2PAD 69                      // row stride (floats) for c2 smem tile

__device__ double g_clash = 0.0;
__device__ double g_pair  = 0.0;
__device__ double g_cnt   = 0.0;
__device__ unsigned int g_done = 0;

__device__ __forceinline__ float fsqrt_approx(float x) {
    float r;
    asm("sqrt.approx.f32 %0, %1;" : "=f"(r) : "f"(x));
    return r;
}

__device__ __forceinline__ float warp_sum(float v) {
    v += __shfl_down_sync(0xffffffffu, v, 16);
    v += __shfl_down_sync(0xffffffffu, v, 8);
    v += __shfl_down_sync(0xffffffffu, v, 4);
    v += __shfl_down_sync(0xffffffffu, v, 2);
    v += __shfl_down_sync(0xffffffffu, v, 1);
    return v;
}

// Core per-tile sweep. DIAG=true masks to j>i within the diagonal tile.
template <bool DIAG>
__device__ __forceinline__ void sweep_tile(
    const float* __restrict__ cmap, int i0, int j0, int tid,
    const float* sxA, const float* syA, const float* szA,
    const float* sxB, const float* syB, const float* szB,
    const float* c2s,
    float& aclash, float& apair, float& acnt)
{
    const int ii = tid >> 4;          // 0..15: base row within pass
    const int jj = tid & 15;          // quad-column index

    // column (B-tile) coords: loaded once, reused across 4 passes
    float xj[4], yj[4], zj[4];
#pragma unroll
    for (int e = 0; e < 4; ++e) {
        xj[e] = sxB[jj * 4 + e];
        yj[e] = syB[jj * 4 + e];
        zj[e] = szB[jj * 4 + e];
    }

    // prefetch all 4 C1 quads (A-rows x B-cols) for MLP
    float4 c1[4];
#pragma unroll
    for (int p = 0; p < 4; ++p)
        c1[p] = __ldg(((const float4*)(cmap + (size_t)(i0 + p * 16 + ii) * L + j0)) + jj);

#pragma unroll
    for (int p = 0; p < 4; ++p) {
        const int iiG = p * 16 + ii;
        const float xi = sxA[iiG], yi = syA[iiG], zi = szA[iiG];   // broadcast LDS
        const float4 cc = c1[p];
        const float c1v[4] = {cc.x, cc.y, cc.z, cc.w};
        float cv2[4];                                              // cv_ji from c2s
#pragma unroll
        for (int e = 0; e < 4; ++e)
            cv2[e] = c2s[(jj * 4 + e) * C2PAD + iiG];

#pragma unroll
        for (int e = 0; e < 4; ++e) {
            float dx = xj[e] - xi;
            float dy = yj[e] - yi;
            float dz = zj[e] - zi;
            float d2 = fmaf(dz, dz, fmaf(dy, dy, dx * dx));
            float d  = fsqrt_approx(d2);
            float t  = fmaxf(3.4f - d, 0.0f);
            float s  = c1v[e] + cv2[e];          // cv_ij + cv_ji
            if (DIAG) {
                float mask = (jj * 4 + e > iiG) ? 1.0f : 0.0f;   // j > i only
                t *= mask;
                s *= mask;
            }
            aclash   = fmaf(t, t, aclash);
            float u  = d - 9.0f;                 // target = 6.0 * 1.5
            float w  = u * s;
            apair    = fmaf(w, u, apair);
        }
        if (!DIAG)                               // C1 ordered-entry count
            acnt += (cc.x + cc.y) + (cc.z + cc.w);
    }
}

__global__ void __launch_bounds__(NTHR, 4)
energy_kernel(const float* __restrict__ coords,
              const float* __restrict__ cmap,
              float* __restrict__ out)
{
    __shared__ float sxA[TS], syA[TS], szA[TS];
    __shared__ float sxB[TS], syB[TS], szB[TS];
    __shared__ float c2s[TS * C2PAD];            // C2 tile, padded rows
    __shared__ float red[32];

    const int tid = threadIdx.x;

    // decode tile pair (A <= B) from linear block index
    int k = blockIdx.x;
    int A = (int)((129.0f - sqrtf(16641.0f - 8.0f * (float)k)) * 0.5f);
    while (64 * (A + 1) - (A + 1) * A / 2 <= k) ++A;
    while (64 * A - A * (A - 1) / 2 > k) --A;
    const int B = A + (k - (64 * A - A * (A - 1) / 2));
    const bool diag = (A == B);
    const int i0 = A * TS;
    const int j0 = B * TS;

    // stage tile coords
    if (tid < TS) {
        sxA[tid] = __ldg(coords + 3 * (i0 + tid) + 0);
        syA[tid] = __ldg(coords + 3 * (i0 + tid) + 1);
        szA[tid] = __ldg(coords + 3 * (i0 + tid) + 2);
    } else if (tid < 2 * TS) {
        const int t = tid - TS;
        sxB[t] = __ldg(coords + 3 * (j0 + t) + 0);
        syB[t] = __ldg(coords + 3 * (j0 + t) + 1);
        szB[t] = __ldg(coords + 3 * (j0 + t) + 2);
    }

    float aclash = 0.0f, apair = 0.0f, acnt = 0.0f;

    // stage C2 = cmap[B-rows][A-cols] (coalesced gmem) into padded smem;
    // its sum counts the B->A ordered entries (for diag: the FULL tile = cnt)
#pragma unroll
    for (int m = 0; m < 4; ++m) {
        const int idx = tid + m * NTHR;
        const int jr  = idx >> 4;                // C2 row (j)
        const int qc  = idx & 15;                // quad col (i)
        float4 v = __ldg(((const float4*)(cmap + (size_t)(j0 + jr) * L + i0)) + qc);
        float* dst = c2s + jr * C2PAD + qc * 4;
        dst[0] = v.x; dst[1] = v.y; dst[2] = v.z; dst[3] = v.w;
        acnt += (v.x + v.y) + (v.z + v.w);
    }
    __syncthreads();

    if (diag) sweep_tile<true >(cmap, i0, j0, tid, sxA, syA, szA, sxB, syB, szB, c2s, aclash, apair, acnt);
    else      sweep_tile<false>(cmap, i0, j0, tid, sxA, syA, szA, sxB, syB, szB, c2s, aclash, apair, acnt);

    // near-band correction (diag blocks own it): remove unordered pairs with
    // j-i in {1,2}. Same expression order as the main loop -> clean cancel.
    if (diag && tid < 2 * TS) {
        const int o = 1 + (tid >> 6);
        const int i = i0 + (tid & 63);
        const int j = i + o;
        if (j < L) {
            float xi = __ldg(coords + 3 * i + 0);
            float yi = __ldg(coords + 3 * i + 1);
            float zi = __ldg(coords + 3 * i + 2);
            float xJ = __ldg(coords + 3 * j + 0);
            float yJ = __ldg(coords + 3 * j + 1);
            float zJ = __ldg(coords + 3 * j + 2);
            float dx = xJ - xi, dy = yJ - yi, dz = zJ - zi;
            float d2 = fmaf(dz, dz, fmaf(dy, dy, dx * dx));
            float d  = fsqrt_approx(d2);
            float t  = fmaxf(3.4f - d, 0.0f);
            aclash   = fmaf(-t, t, aclash);
            float s  = __ldg(cmap + (size_t)i * L + j) + __ldg(cmap + (size_t)j * L + i);
            float u  = d - 9.0f;
            float w  = u * s;
            apair    = fmaf(-w, u, apair);
        }
    }

    // block reduction
    aclash = warp_sum(aclash);
    apair  = warp_sum(apair);
    acnt   = warp_sum(acnt);
    const int wid  = tid >> 5;
    const int lane = tid & 31;
    if (lane == 0) {
        red[wid]      = aclash;
        red[8 + wid]  = apair;
        red[16 + wid] = acnt;
    }
    __syncthreads();
    if (tid == 0) {
        float cs = 0.0f, ps = 0.0f, ns = 0.0f;
        for (int w = 0; w < 8; ++w) { cs += red[w]; ps += red[8 + w]; ns += red[16 + w]; }
        atomicAdd(&g_clash, (double)cs);
        atomicAdd(&g_pair,  (double)ps);
        atomicAdd(&g_cnt,   (double)ns);
        __threadfence();
        unsigned prev = atomicAdd(&g_done, 1u);
        red[24] = (prev == (unsigned)(NBLK - 1)) ? 1.0f : 0.0f;
    }
    __syncthreads();

    // last block: bond term + finalize + reset for next graph replay
    if (red[24] != 0.0f) {
        float b = 0.0f;
        for (int k2 = tid; k2 < L - 1; k2 += NTHR) {
            float dx = __ldg(coords + 3 * k2 + 3) - __ldg(coords + 3 * k2 + 0);
            float dy = __ldg(coords + 3 * k2 + 4) - __ldg(coords + 3 * k2 + 1);
            float dz = __ldg(coords + 3 * k2 + 5) - __ldg(coords + 3 * k2 + 2);
            float d  = fsqrt_approx(fmaf(dz, dz, fmaf(dy, dy, dx * dx)));
            float t  = d - 6.0f;                 // IDEAL_C1_C1
            b = fmaf(t, t, b);
        }
        b = warp_sum(b);
        __syncthreads();
        if (lane == 0) red[wid] = b;
        __syncthreads();
        if (tid == 0) {
            float bs = 0.0f;
            for (int w = 0; w < 8; ++w) bs += red[w];
            double e_bond  = (double)bs / (double)(L - 1);
            double e_clash = g_clash / (double)L;   // unordered j>=i+3, counted once
            double cnt     = g_cnt < 1.0 ? 1.0 : g_cnt;
            double e_pair  = g_pair / cnt;
            out[0] = (float)(e_bond + 2.0 * e_clash + 0.5 * e_pair);
            g_clash = 0.0;
            g_pair  = 0.0;
            g_cnt   = 0.0;
            g_done  = 0u;
        }
    }
}

extern "C" void kernel_launch(void* const* d_in, const int* in_sizes, int n_in,
                              void* d_out, int out_size) {
    const float* a0 = (const float*)d_in[0];
    const float* a1 = (const float*)d_in[1];
    // coords is the small input (L*3), contact_map the big one (L*L)
    const float* coords = (in_sizes[0] < in_sizes[1]) ? a0 : a1;
    const float* cmap   = (in_sizes[0] < in_sizes[1]) ? a1 : a0;
    energy_kernel<<<NBLK, NTHR>>>(coords, cmap, (float*)d_out);
}